// round 1
// baseline (speedup 1.0000x reference)
#include <cuda_runtime.h>
#include <math.h>

// Problem constants
#define Bb 16
#define Tt 2048
#define Cc 512
#define Hh 4
#define Kk 31
#define Mm (Bb * Tt)        // 32768 rows

// ---------------- scratch (device globals: allocation-free) ----------------
__device__ float g_y1[(size_t)Mm * (2 * Cc)];   // pre-GLU GEMM1 output, 128 MB
__device__ float g_z[(size_t)Mm * Cc];          // post-conv, 64 MB

// ---------------- GEMM: C[M,N] = A[M,K] @ B[N,K]^T + bias[N] ----------------
// A row-major (K contiguous), B row-major (K contiguous). M,N multiples of 128,
// K multiple of 16.
#define BM 128
#define BN 128
#define BK 16

__global__ __launch_bounds__(256, 2) void gemm_tn_kernel(
    const float* __restrict__ A, const float* __restrict__ B,
    const float* __restrict__ bias, float* __restrict__ C,
    int M, int N, int K)
{
    __shared__ float As[BK][BM + 4];
    __shared__ float Bs[BK][BN + 4];

    const int tid = threadIdx.x;
    const int tx = tid & 15;       // 0..15 -> N
    const int ty = tid >> 4;       // 0..15 -> M
    const int m0 = blockIdx.y * BM;
    const int n0 = blockIdx.x * BN;

    const int lr = tid >> 2;       // 0..63  load row
    const int lv = tid & 3;        // 0..3   load vec (16B)

    float acc[8][8];
#pragma unroll
    for (int i = 0; i < 8; i++)
#pragma unroll
        for (int j = 0; j < 8; j++) acc[i][j] = 0.f;

    for (int kt = 0; kt < K; kt += BK) {
#pragma unroll
        for (int s = 0; s < 2; s++) {
            const int r = lr + s * 64;
            float4 va = *(const float4*)&A[(size_t)(m0 + r) * K + kt + lv * 4];
            As[lv * 4 + 0][r] = va.x;
            As[lv * 4 + 1][r] = va.y;
            As[lv * 4 + 2][r] = va.z;
            As[lv * 4 + 3][r] = va.w;
            float4 vb = *(const float4*)&B[(size_t)(n0 + r) * K + kt + lv * 4];
            Bs[lv * 4 + 0][r] = vb.x;
            Bs[lv * 4 + 1][r] = vb.y;
            Bs[lv * 4 + 2][r] = vb.z;
            Bs[lv * 4 + 3][r] = vb.w;
        }
        __syncthreads();

#pragma unroll
        for (int kk = 0; kk < BK; kk++) {
            float a[8], b[8];
            *(float4*)&a[0] = *(const float4*)&As[kk][ty * 4];
            *(float4*)&a[4] = *(const float4*)&As[kk][64 + ty * 4];
            *(float4*)&b[0] = *(const float4*)&Bs[kk][tx * 4];
            *(float4*)&b[4] = *(const float4*)&Bs[kk][64 + tx * 4];
#pragma unroll
            for (int i = 0; i < 8; i++)
#pragma unroll
                for (int j = 0; j < 8; j++)
                    acc[i][j] += a[i] * b[j];
        }
        __syncthreads();
    }

    // epilogue: + bias, float4 stores
#pragma unroll
    for (int jn = 0; jn < 2; jn++) {
        const int gn = n0 + jn * 64 + tx * 4;
        const float4 bb = *(const float4*)&bias[gn];
#pragma unroll
        for (int im = 0; im < 2; im++)
#pragma unroll
            for (int i = 0; i < 4; i++) {
                const int gm = m0 + im * 64 + ty * 4 + i;
                float4 v;
                v.x = acc[im * 4 + i][jn * 4 + 0] + bb.x;
                v.y = acc[im * 4 + i][jn * 4 + 1] + bb.y;
                v.z = acc[im * 4 + i][jn * 4 + 2] + bb.z;
                v.w = acc[im * 4 + i][jn * 4 + 3] + bb.w;
                *(float4*)&C[(size_t)gm * N + gn] = v;
            }
    }
}

// ---------------- GLU + depthwise LightConv fused kernel ----------------
// Reads y1 (M x 1024): a = y1[:, :512], g = y1[:, 512:]; glu = a*sigmoid(g)
// applied once at the smem load stage. Then per-channel depthwise conv along
// T (within one batch), kernel = softmax(lconv_weight[c%4]), + lconv_bias[c].
// Tile: 64 t x 64 c, halo 15 each side. 256 threads.
#define TT 64
#define TC 64
#define PAD 15
#define SROWS (TT + 2 * PAD)   // 94

__global__ __launch_bounds__(256, 4) void lconv_glu_kernel(
    const float* __restrict__ y1, const float* __restrict__ lw,
    const float* __restrict__ lbias, float* __restrict__ z)
{
    __shared__ float s[SROWS][TC];
    __shared__ float wk[Hh][Kk];

    const int tid = threadIdx.x;
    const int t0 = blockIdx.x * TT;
    const int c0 = blockIdx.y * TC;
    const int b  = blockIdx.z;

    // softmax of the 4 shared kernels (redundant per block, trivial cost)
    if (tid < Hh) {
        float mx = -1e30f;
#pragma unroll
        for (int k = 0; k < Kk; k++) mx = fmaxf(mx, lw[tid * Kk + k]);
        float sum = 0.f;
        float e[Kk];
#pragma unroll
        for (int k = 0; k < Kk; k++) { e[k] = __expf(lw[tid * Kk + k] - mx); sum += e[k]; }
        const float inv = 1.f / sum;
#pragma unroll
        for (int k = 0; k < Kk; k++) wk[tid][k] = e[k] * inv;
    }

    // load tile with halo, fusing GLU
    const float* yb = y1 + (size_t)b * Tt * (2 * Cc);
    for (int idx = tid; idx < SROWS * (TC / 4); idx += 256) {
        const int r = idx / (TC / 4);
        const int v = idx % (TC / 4);
        const int t = t0 - PAD + r;
        float4 o;
        if (t >= 0 && t < Tt) {
            const float4 a4 = *(const float4*)&yb[(size_t)t * (2 * Cc) + c0 + v * 4];
            const float4 g4 = *(const float4*)&yb[(size_t)t * (2 * Cc) + Cc + c0 + v * 4];
            o.x = a4.x * (1.f / (1.f + __expf(-g4.x)));
            o.y = a4.y * (1.f / (1.f + __expf(-g4.y)));
            o.z = a4.z * (1.f / (1.f + __expf(-g4.z)));
            o.w = a4.w * (1.f / (1.f + __expf(-g4.w)));
        } else {
            o.x = o.y = o.z = o.w = 0.f;
        }
        *(float4*)&s[r][v * 4] = o;
    }
    __syncthreads();

    // compute: each thread owns one channel, 16 consecutive t rows
    const int cl = tid & (TC - 1);          // 0..63
    const int tg = tid >> 6;                // 0..3
    const int h  = cl & (Hh - 1);           // (c0+cl)%4, c0 multiple of 4

    float wr[Kk];
#pragma unroll
    for (int k = 0; k < Kk; k++) wr[k] = wk[h][k];
    const float bv = lbias[c0 + cl];

    float* zb = z + ((size_t)b * Tt + t0) * Cc + c0 + cl;
#pragma unroll
    for (int i = 0; i < 16; i++) {
        const int tl = tg * 16 + i;
        float acc = bv;
#pragma unroll
        for (int k = 0; k < Kk; k++)
            acc += wr[k] * s[tl + k][cl];
        zb[(size_t)tl * Cc] = acc;
    }
}

// ---------------- launch ----------------
extern "C" void kernel_launch(void* const* d_in, const int* in_sizes, int n_in,
                              void* d_out, int out_size)
{
    const float* x     = (const float*)d_in[0];
    const float* lw    = (const float*)d_in[1];
    const float* lbias = (const float*)d_in[2];
    const float* w1    = (const float*)d_in[3];
    const float* b1    = (const float*)d_in[4];
    const float* w2    = (const float*)d_in[5];
    const float* b2    = (const float*)d_in[6];
    float* out = (float*)d_out;

    float *y1p = nullptr, *zp = nullptr;
    cudaGetSymbolAddress((void**)&y1p, g_y1);
    cudaGetSymbolAddress((void**)&zp, g_z);

    // GEMM1: (32768 x 1024) = x @ w1^T + b1
    gemm_tn_kernel<<<dim3((2 * Cc) / BN, Mm / BM), 256>>>(
        x, w1, b1, y1p, Mm, 2 * Cc, Cc);

    // GLU + LightConv + bias
    lconv_glu_kernel<<<dim3(Tt / TT, Cc / TC, Bb), 256>>>(y1p, lw, lbias, zp);

    // GEMM2: (32768 x 512) = z @ w2^T + b2
    gemm_tn_kernel<<<dim3(Cc / BN, Mm / BM), 256>>>(
        zp, w2, b2, out, Mm, Cc, Cc);
}

// round 3
// speedup vs baseline: 1.5798x; 1.5798x over previous
#include <cuda_runtime.h>
#include <cstdint>
#include <math.h>

// Problem constants
#define Bb 16
#define Tt 2048
#define Cc 512
#define Hh 4
#define Kk 31
#define Mm (Bb * Tt)        // 32768 rows

// ---------------- scratch (device globals: allocation-free) ----------------
__device__ float g_glu[(size_t)Mm * Cc];   // GLU output, 64 MB
__device__ float g_z[(size_t)Mm * Cc];     // post-conv, 64 MB

static __device__ __forceinline__ uint32_t f2tf32(float f) {
    uint32_t u;
    asm("cvt.rna.tf32.f32 %0, %1;" : "=r"(u) : "f"(f));
    return u;
}

// ---------------- tf32 mma.sync GEMM ----------------
// C[M,N] = A[M,K] @ B[N,K]^T (+bias, +optional GLU).  A,B row-major (K contig).
// CTA: 128x128 acc tile, BK=32 (4 mma k-steps of 8), 256 threads = 8 warps
// of 32(m)x64(n).  Smem layout per buffer: [s=0..3][row=0..127][c=0..3] of
// float2 (k = s*8+c, k = s*8+c+4) so fragment loads are single LDS.64,
// conflict-free.  Double buffered: 2 x (16KB A + 16KB B) = 64KB dynamic.
//
// GLU mode: CTA covers glu cols [bx*64, bx*64+64); B rows are w1 rows
// {bx*64+j} (a) and {512+bx*64+j} (g).  n-tiles 0..3 = a, 4..7 = g (same
// output columns), epilogue emits a*sigmoid(g).
#define GEMM_SMEM 65536

template<bool GLU>
__global__ void __launch_bounds__(256) gemm_tf32(
    const float* __restrict__ A, const float* __restrict__ Bw,
    const float* __restrict__ bias, float* __restrict__ C)
{
    extern __shared__ __align__(16) uint32_t sm[];   // indexed in float2 units via uint2*/uint4*
    const int tid  = threadIdx.x;
    const int lane = tid & 31;
    const int wid  = tid >> 5;
    const int wm   = wid & 3;        // warp m: 0..3 (32 rows each)
    const int wn   = wid >> 2;       // warp n: 0..1 (64 cols each)
    const int bc   = lane & 3;       // fragment k-pair index
    const int lq   = lane >> 2;      // fragment row/col-within-8
    const int m0   = blockIdx.y * 128;
    const int colbase = blockIdx.x * (GLU ? 64 : 128);
    const int K = Cc;                // 512 for both GEMMs
    const int NK = K / 32;           // 16 chunks

    // ---- loader setup: tid<128 -> A row, tid>=128 -> B row ----
    const int lr = tid & 127;
    const float* gp;
    if (tid < 128) {
        gp = A + (size_t)(m0 + lr) * K;
    } else {
        int n;
        if (GLU) n = (lr < 64) ? (colbase + lr) : (512 + colbase + (lr - 64));
        else     n = colbase + lr;
        gp = Bw + (size_t)n * K;
    }
    const uint32_t sb_f2 = (tid < 128) ? 0u : 2048u;   // float2 base in buffer

    float4 lo[4], hi[4];
    float acc[2][8][4];
#pragma unroll
    for (int mt = 0; mt < 2; mt++)
#pragma unroll
        for (int nt = 0; nt < 8; nt++)
#pragma unroll
            for (int i = 0; i < 4; i++) acc[mt][nt][i] = 0.f;

    auto ldg = [&](int kt) {
#pragma unroll
        for (int s = 0; s < 4; s++) {
            lo[s] = *(const float4*)(gp + kt * 32 + s * 8);
            hi[s] = *(const float4*)(gp + kt * 32 + s * 8 + 4);
        }
    };
    auto sts = [&](int buf) {
#pragma unroll
        for (int s = 0; s < 4; s++) {
            uint4 q0 = make_uint4(f2tf32(lo[s].x), f2tf32(hi[s].x),
                                  f2tf32(lo[s].y), f2tf32(hi[s].y));
            uint4 q1 = make_uint4(f2tf32(lo[s].z), f2tf32(hi[s].z),
                                  f2tf32(lo[s].w), f2tf32(hi[s].w));
            uint32_t i4 = (uint32_t)(buf * 4096 + sb_f2 + (s * 128 + lr) * 4) >> 1;
            ((uint4*)sm)[i4]     = q0;
            ((uint4*)sm)[i4 + 1] = q1;
        }
    };

    ldg(0);
    sts(0);

#pragma unroll 1
    for (int kt = 0; kt < NK; kt++) {
        __syncthreads();
        if (kt + 1 < NK) ldg(kt + 1);

        const int bufo = (kt & 1) * 4096;
#pragma unroll
        for (int s = 0; s < 4; s++) {
            uint32_t Af[2][4];
#pragma unroll
            for (int mt = 0; mt < 2; mt++) {
                const int r0 = wm * 32 + mt * 16 + lq;
                uint2 v0 = ((const uint2*)sm)[bufo + (s * 128 + r0) * 4 + bc];
                uint2 v1 = ((const uint2*)sm)[bufo + (s * 128 + r0 + 8) * 4 + bc];
                Af[mt][0] = v0.x; Af[mt][2] = v0.y;
                Af[mt][1] = v1.x; Af[mt][3] = v1.y;
            }
#pragma unroll
            for (int nt = 0; nt < 8; nt++) {
                const int br = (nt >> 2) * 64 + wn * 32 + (nt & 3) * 8 + lq;
                uint2 bv = ((const uint2*)sm)[bufo + 2048 + (s * 128 + br) * 4 + bc];
#pragma unroll
                for (int mt = 0; mt < 2; mt++) {
                    asm volatile(
                        "mma.sync.aligned.m16n8k8.row.col.f32.tf32.tf32.f32 "
                        "{%0,%1,%2,%3}, {%4,%5,%6,%7}, {%8,%9}, {%0,%1,%2,%3};"
                        : "+f"(acc[mt][nt][0]), "+f"(acc[mt][nt][1]),
                          "+f"(acc[mt][nt][2]), "+f"(acc[mt][nt][3])
                        : "r"(Af[mt][0]), "r"(Af[mt][1]),
                          "r"(Af[mt][2]), "r"(Af[mt][3]),
                          "r"(bv.x), "r"(bv.y));
                }
            }
        }
        if (kt + 1 < NK) sts((kt + 1) & 1);
    }

    // ---- epilogue ----
    const int r0 = m0 + wm * 32 + lq;
    if (GLU) {
#pragma unroll
        for (int mt = 0; mt < 2; mt++) {
#pragma unroll
            for (int nt = 0; nt < 4; nt++) {
                const int col = colbase + wn * 32 + nt * 8 + bc * 2;
                const float2 ba = *(const float2*)&bias[col];
                const float2 bg = *(const float2*)&bias[512 + col];
                const int r = r0 + mt * 16;
                float a0 = acc[mt][nt][0] + ba.x,  a1 = acc[mt][nt][1] + ba.y;
                float g0 = acc[mt][nt + 4][0] + bg.x, g1 = acc[mt][nt + 4][1] + bg.y;
                float2 o;
                o.x = a0 / (1.f + __expf(-g0));
                o.y = a1 / (1.f + __expf(-g1));
                *(float2*)&C[(size_t)r * Cc + col] = o;
                a0 = acc[mt][nt][2] + ba.x;  a1 = acc[mt][nt][3] + ba.y;
                g0 = acc[mt][nt + 4][2] + bg.x; g1 = acc[mt][nt + 4][3] + bg.y;
                o.x = a0 / (1.f + __expf(-g0));
                o.y = a1 / (1.f + __expf(-g1));
                *(float2*)&C[(size_t)(r + 8) * Cc + col] = o;
            }
        }
    } else {
#pragma unroll
        for (int mt = 0; mt < 2; mt++) {
#pragma unroll
            for (int nt = 0; nt < 8; nt++) {
                const int col = colbase + (nt >> 2) * 64 + wn * 32 + (nt & 3) * 8 + bc * 2;
                const float2 bb = *(const float2*)&bias[col];
                const int r = r0 + mt * 16;
                float2 o;
                o.x = acc[mt][nt][0] + bb.x;
                o.y = acc[mt][nt][1] + bb.y;
                *(float2*)&C[(size_t)r * Cc + col] = o;
                o.x = acc[mt][nt][2] + bb.x;
                o.y = acc[mt][nt][3] + bb.y;
                *(float2*)&C[(size_t)(r + 8) * Cc + col] = o;
            }
        }
    }
}

// ---------------- depthwise LightConv kernel (R1-verified, GLU removed) ----------------
#define TT 64
#define TC 64
#define PAD 15
#define SROWS (TT + 2 * PAD)   // 94

__global__ __launch_bounds__(256, 4) void lconv_kernel(
    const float* __restrict__ glu, const float* __restrict__ lw,
    const float* __restrict__ lbias, float* __restrict__ z)
{
    __shared__ float s[SROWS][TC];
    __shared__ float wk[Hh][Kk];

    const int tid = threadIdx.x;
    const int t0 = blockIdx.x * TT;
    const int c0 = blockIdx.y * TC;
    const int b  = blockIdx.z;

    if (tid < Hh) {
        float mx = -1e30f;
#pragma unroll
        for (int k = 0; k < Kk; k++) mx = fmaxf(mx, lw[tid * Kk + k]);
        float sum = 0.f;
        float e[Kk];
#pragma unroll
        for (int k = 0; k < Kk; k++) { e[k] = __expf(lw[tid * Kk + k] - mx); sum += e[k]; }
        const float inv = 1.f / sum;
#pragma unroll
        for (int k = 0; k < Kk; k++) wk[tid][k] = e[k] * inv;
    }

    const float* yb = glu + (size_t)b * Tt * Cc;
    for (int idx = tid; idx < SROWS * (TC / 4); idx += 256) {
        const int r = idx / (TC / 4);
        const int v = idx % (TC / 4);
        const int t = t0 - PAD + r;
        float4 o;
        if (t >= 0 && t < Tt) {
            o = *(const float4*)&yb[(size_t)t * Cc + c0 + v * 4];
        } else {
            o.x = o.y = o.z = o.w = 0.f;
        }
        *(float4*)&s[r][v * 4] = o;
    }
    __syncthreads();

    const int cl = tid & (TC - 1);
    const int tg = tid >> 6;
    const int h  = cl & (Hh - 1);

    float wr[Kk];
#pragma unroll
    for (int k = 0; k < Kk; k++) wr[k] = wk[h][k];
    const float bv = lbias[c0 + cl];

    float* zb = z + ((size_t)b * Tt + t0) * Cc + c0 + cl;
#pragma unroll
    for (int i = 0; i < 16; i++) {
        const int tl = tg * 16 + i;
        float acc = bv;
#pragma unroll
        for (int k = 0; k < Kk; k++)
            acc += wr[k] * s[tl + k][cl];
        zb[(size_t)tl * Cc] = acc;
    }
}

// ---------------- launch ----------------
extern "C" void kernel_launch(void* const* d_in, const int* in_sizes, int n_in,
                              void* d_out, int out_size)
{
    const float* x     = (const float*)d_in[0];
    const float* lw    = (const float*)d_in[1];
    const float* lbias = (const float*)d_in[2];
    const float* w1    = (const float*)d_in[3];
    const float* b1    = (const float*)d_in[4];
    const float* w2    = (const float*)d_in[5];
    const float* b2    = (const float*)d_in[6];
    float* out = (float*)d_out;

    float *glup = nullptr, *zp = nullptr;
    cudaGetSymbolAddress((void**)&glup, g_glu);
    cudaGetSymbolAddress((void**)&zp, g_z);

    cudaFuncSetAttribute(gemm_tf32<true>,
                         cudaFuncAttributeMaxDynamicSharedMemorySize, GEMM_SMEM);
    cudaFuncSetAttribute(gemm_tf32<false>,
                         cudaFuncAttributeMaxDynamicSharedMemorySize, GEMM_SMEM);

    // GEMM1 + bias + GLU: (32768 x 512 glu) from x @ w1^T
    gemm_tf32<true><<<dim3(Cc / 64, Mm / 128), 256, GEMM_SMEM>>>(x, w1, b1, glup);

    // depthwise LightConv + bias
    lconv_kernel<<<dim3(Tt / TT, Cc / TC, Bb), 256>>>(glup, lw, lbias, zp);

    // GEMM2 + bias: (32768 x 512) = z @ w2^T + b2
    gemm_tf32<false><<<dim3(Cc / 128, Mm / 128), 256, GEMM_SMEM>>>(zp, w2, b2, out);
}

// round 4
// speedup vs baseline: 2.2456x; 1.4214x over previous
#include <cuda_runtime.h>
#include <cstdint>
#include <math.h>

// Problem constants
#define Bb 16
#define Tt 2048
#define Cc 512
#define Hh 4
#define Kk 31
#define Mm (Bb * Tt)        // 32768 rows

// ---------------- scratch (device globals: allocation-free) ----------------
__device__ float g_xc[(size_t)Mm * Cc];       // tf32-rounded x, 64 MB
__device__ float g_w1c[(size_t)2 * Cc * Cc];  // tf32-rounded w1, 2 MB
__device__ float g_w2c[(size_t)Cc * Cc];      // tf32-rounded w2, 1 MB
__device__ float g_glu[(size_t)Mm * Cc];      // GLU output (fp32), 64 MB
__device__ float g_z[(size_t)Mm * Cc];        // post-conv (tf32-rounded), 64 MB

static __device__ __forceinline__ float f2tf32(float f) {
    uint32_t u;
    asm("cvt.rna.tf32.f32 %0, %1;" : "=r"(u) : "f"(f));
    return __uint_as_float(u);
}

// ---------------- prepass: rna-round to tf32 bit pattern ----------------
__global__ void __launch_bounds__(256) cvt_kernel(
    const float* __restrict__ in, float* __restrict__ out, int n4)
{
    int i = blockIdx.x * blockDim.x + threadIdx.x;
    if (i < n4) {
        float4 v = ((const float4*)in)[i];
        v.x = f2tf32(v.x); v.y = f2tf32(v.y);
        v.z = f2tf32(v.z); v.w = f2tf32(v.w);
        ((float4*)out)[i] = v;
    }
}

// ---------------- tf32 mma.sync GEMM, 64x64 warp tiles ----------------
// C[M,N] = A[M,K] @ B[N,K]^T + bias (+GLU).  A,B row-major K-contiguous,
// pre-rounded to tf32.  CTA: 128x128 tile, 128 threads = 4 warps (2x2 of
// 64x64).  BK=16, double-buffered smem, one sync per chunk.
//
// Smem layout per buffer (4096 floats): A rows 0..127 x 16 floats, then B.
// Row = 16 floats natural k-order, stored as 4x 16B units with XOR swizzle:
//   float_idx(row,k) = row*16 + ((k>>2) ^ (row&3))*4 + (k&3)
// mma k-relabel: mma slot bc <-> storage 2bc, slot bc+4 <-> storage 2bc+1
// (same bijection for A and B => dot product unchanged).
//
// GLU mode: BN covers 64 a-cols + 64 matching g-cols of w1, interleaved so
// each warp owns 32 (a,g) pairs; epilogue emits a*sigmoid(g).

template<bool GLU>
__global__ void __launch_bounds__(128, 2) gemm_mma(
    const float* __restrict__ A, const float* __restrict__ Bw,
    const float* __restrict__ bias, float* __restrict__ C)
{
    __shared__ float sm[8192];
    const int tid  = threadIdx.x;
    const int lane = tid & 31;
    const int wid  = tid >> 5;
    const int wm   = wid & 1;        // warp m: 0..1 (64 rows)
    const int wn   = wid >> 1;       // warp n: 0..1 (64 cols)
    const int bc   = lane & 3;
    const int lq   = lane >> 2;
    const int m0   = blockIdx.y * 128;
    const int colbase = blockIdx.x * (GLU ? 64 : 128);

    // ---- producer: thread t -> (row prow+32j, 16B unit punit), A and B ----
    const int prow  = tid >> 2;
    const int punit = tid & 3;
    const int swu   = ((punit ^ (prow & 3)) << 2);   // swizzled unit offset
    const float* gA = A + (size_t)(m0 + prow) * Cc + punit * 4;
    const float* gBp[4];
#pragma unroll
    for (int j = 0; j < 4; j++) {
        const int r = prow + 32 * j;
        int br;
        if (GLU) {
            const int g = r >> 6, w = r & 63;
            br = (w < 32) ? (colbase + g * 32 + w)
                          : (512 + colbase + g * 32 + (w - 32));
        } else {
            br = colbase + r;
        }
        gBp[j] = Bw + (size_t)br * Cc + punit * 4;
    }

    float4 stA[4], stB[4];
    float acc[4][8][4];
#pragma unroll
    for (int mt = 0; mt < 4; mt++)
#pragma unroll
        for (int nt = 0; nt < 8; nt++)
#pragma unroll
            for (int i = 0; i < 4; i++) acc[mt][nt][i] = 0.f;

    // fragment address pieces (float offsets within buffer)
    const int lq3   = lq & 3;
    const int bchi  = bc >> 1;
    const int bclo2 = (bc & 1) * 2;

    const int NK = Cc / 16;   // 32 chunks

    // prologue
#pragma unroll
    for (int j = 0; j < 4; j++) {
        stA[j] = *(const float4*)(gA + (size_t)(32 * j) * Cc);
        stB[j] = *(const float4*)(gBp[j]);
    }
#pragma unroll
    for (int j = 0; j < 4; j++) {
        const int off = (prow + 32 * j) * 16 + swu;
        *(float4*)(sm + off)        = stA[j];
        *(float4*)(sm + 2048 + off) = stB[j];
    }

#pragma unroll 1
    for (int kt = 0; kt < NK; kt++) {
        __syncthreads();
        if (kt + 1 < NK) {
#pragma unroll
            for (int j = 0; j < 4; j++) {
                stA[j] = *(const float4*)(gA + (size_t)(32 * j) * Cc + (kt + 1) * 16);
                stB[j] = *(const float4*)(gBp[j] + (kt + 1) * 16);
            }
        }

        const float* s0 = sm + (kt & 1) * 4096;
#pragma unroll
        for (int s = 0; s < 2; s++) {
            const int uo = (((s * 2 + bchi) ^ lq3) << 2) + bclo2;
            // A fragments: 4 m-tiles
            float af[4][4];
#pragma unroll
            for (int mt = 0; mt < 4; mt++) {
                const int r = wm * 64 + mt * 16 + lq;
                const float2 v0 = *(const float2*)(s0 + r * 16 + uo);
                const float2 v1 = *(const float2*)(s0 + (r + 8) * 16 + uo);
                af[mt][0] = v0.x; af[mt][1] = v1.x;
                af[mt][2] = v0.y; af[mt][3] = v1.y;
            }
#pragma unroll
            for (int nt = 0; nt < 8; nt++) {
                const int rb = wn * 64 + nt * 8 + lq;
                const float2 bv = *(const float2*)(s0 + 2048 + rb * 16 + uo);
#pragma unroll
                for (int mt = 0; mt < 4; mt++) {
                    asm volatile(
                        "mma.sync.aligned.m16n8k8.row.col.f32.tf32.tf32.f32 "
                        "{%0,%1,%2,%3}, {%4,%5,%6,%7}, {%8,%9}, {%0,%1,%2,%3};"
                        : "+f"(acc[mt][nt][0]), "+f"(acc[mt][nt][1]),
                          "+f"(acc[mt][nt][2]), "+f"(acc[mt][nt][3])
                        : "r"(__float_as_uint(af[mt][0])), "r"(__float_as_uint(af[mt][1])),
                          "r"(__float_as_uint(af[mt][2])), "r"(__float_as_uint(af[mt][3])),
                          "r"(__float_as_uint(bv.x)), "r"(__float_as_uint(bv.y)));
                }
            }
        }

        if (kt + 1 < NK) {
            float* s1 = sm + ((kt + 1) & 1) * 4096;
#pragma unroll
            for (int j = 0; j < 4; j++) {
                const int off = (prow + 32 * j) * 16 + swu;
                *(float4*)(s1 + off)        = stA[j];
                *(float4*)(s1 + 2048 + off) = stB[j];
            }
        }
    }

    // ---- epilogue ----
    if (GLU) {
#pragma unroll
        for (int mt = 0; mt < 4; mt++) {
            const int r = m0 + wm * 64 + mt * 16 + lq;
#pragma unroll
            for (int nt = 0; nt < 4; nt++) {
                const int col = colbase + wn * 32 + nt * 8 + bc * 2;
                const float2 ba = *(const float2*)&bias[col];
                const float2 bg = *(const float2*)&bias[512 + col];
                float2 o;
                {
                    const float a0 = acc[mt][nt][0] + ba.x, a1 = acc[mt][nt][1] + ba.y;
                    const float g0 = acc[mt][nt + 4][0] + bg.x, g1 = acc[mt][nt + 4][1] + bg.y;
                    o.x = a0 / (1.f + __expf(-g0));
                    o.y = a1 / (1.f + __expf(-g1));
                    *(float2*)&C[(size_t)r * Cc + col] = o;
                }
                {
                    const float a0 = acc[mt][nt][2] + ba.x, a1 = acc[mt][nt][3] + ba.y;
                    const float g0 = acc[mt][nt + 4][2] + bg.x, g1 = acc[mt][nt + 4][3] + bg.y;
                    o.x = a0 / (1.f + __expf(-g0));
                    o.y = a1 / (1.f + __expf(-g1));
                    *(float2*)&C[(size_t)(r + 8) * Cc + col] = o;
                }
            }
        }
    } else {
#pragma unroll
        for (int mt = 0; mt < 4; mt++) {
            const int r = m0 + wm * 64 + mt * 16 + lq;
#pragma unroll
            for (int nt = 0; nt < 8; nt++) {
                const int col = colbase + wn * 64 + nt * 8 + bc * 2;
                const float2 bb = *(const float2*)&bias[col];
                float2 o;
                o.x = acc[mt][nt][0] + bb.x;
                o.y = acc[mt][nt][1] + bb.y;
                *(float2*)&C[(size_t)r * Cc + col] = o;
                o.x = acc[mt][nt][2] + bb.x;
                o.y = acc[mt][nt][3] + bb.y;
                *(float2*)&C[(size_t)(r + 8) * Cc + col] = o;
            }
        }
    }
}

// ---------------- depthwise LightConv (register sliding window) ----------------
#define TT 64
#define TC 64
#define PAD 15
#define SROWS (TT + 2 * PAD)   // 94

__global__ __launch_bounds__(256, 4) void lconv_kernel(
    const float* __restrict__ glu, const float* __restrict__ lw,
    const float* __restrict__ lbias, float* __restrict__ z)
{
    __shared__ float s[SROWS][TC];
    __shared__ float wk[Hh][Kk];

    const int tid = threadIdx.x;
    const int t0 = blockIdx.x * TT;
    const int c0 = blockIdx.y * TC;
    const int b  = blockIdx.z;

    if (tid < Hh) {
        float mx = -1e30f;
#pragma unroll
        for (int k = 0; k < Kk; k++) mx = fmaxf(mx, lw[tid * Kk + k]);
        float sum = 0.f;
        float e[Kk];
#pragma unroll
        for (int k = 0; k < Kk; k++) { e[k] = __expf(lw[tid * Kk + k] - mx); sum += e[k]; }
        const float inv = 1.f / sum;
#pragma unroll
        for (int k = 0; k < Kk; k++) wk[tid][k] = e[k] * inv;
    }

    const float* yb = glu + (size_t)b * Tt * Cc;
    for (int idx = tid; idx < SROWS * (TC / 4); idx += 256) {
        const int r = idx / (TC / 4);
        const int v = idx % (TC / 4);
        const int t = t0 - PAD + r;
        float4 o;
        if (t >= 0 && t < Tt) {
            o = *(const float4*)&yb[(size_t)t * Cc + c0 + v * 4];
        } else {
            o.x = o.y = o.z = o.w = 0.f;
        }
        *(float4*)&s[r][v * 4] = o;
    }
    __syncthreads();

    const int cl = tid & (TC - 1);
    const int tg = tid >> 6;       // 0..3, owns rows tg*16 .. tg*16+15
    const int h  = cl & (Hh - 1);

    float wr[Kk];
#pragma unroll
    for (int k = 0; k < Kk; k++) wr[k] = wk[h][k];
    const float bv = lbias[c0 + cl];

    // scatter-accumulate: 47 smem reads feed 16 outputs x 31 taps
    float acc[16];
#pragma unroll
    for (int i = 0; i < 16; i++) acc[i] = bv;
#pragma unroll
    for (int jj = 0; jj < TT / 4 + Kk - 1; jj++) {   // 46+1 = 47 window elems
        const float v = s[tg * 16 + jj][cl];
        const int ilo = (jj - (Kk - 1)) > 0 ? (jj - (Kk - 1)) : 0;
        const int ihi = jj < 15 ? jj : 15;
#pragma unroll
        for (int i = ilo; i <= ihi; i++)
            acc[i] += wr[jj - i] * v;
    }

    float* zb = z + ((size_t)b * Tt + t0 + tg * 16) * Cc + c0 + cl;
#pragma unroll
    for (int i = 0; i < 16; i++)
        zb[(size_t)i * Cc] = f2tf32(acc[i]);
}

// ---------------- launch ----------------
extern "C" void kernel_launch(void* const* d_in, const int* in_sizes, int n_in,
                              void* d_out, int out_size)
{
    const float* x     = (const float*)d_in[0];
    const float* lw    = (const float*)d_in[1];
    const float* lbias = (const float*)d_in[2];
    const float* w1    = (const float*)d_in[3];
    const float* b1    = (const float*)d_in[4];
    const float* w2    = (const float*)d_in[5];
    const float* b2    = (const float*)d_in[6];
    float* out = (float*)d_out;

    float *xc, *w1c, *w2c, *glup, *zp;
    cudaGetSymbolAddress((void**)&xc,   g_xc);
    cudaGetSymbolAddress((void**)&w1c,  g_w1c);
    cudaGetSymbolAddress((void**)&w2c,  g_w2c);
    cudaGetSymbolAddress((void**)&glup, g_glu);
    cudaGetSymbolAddress((void**)&zp,   g_z);

    // prepass: rna-round inputs once
    cvt_kernel<<<(Mm * Cc / 4 + 255) / 256, 256>>>(x, xc, Mm * Cc / 4);
    cvt_kernel<<<(2 * Cc * Cc / 4 + 255) / 256, 256>>>(w1, w1c, 2 * Cc * Cc / 4);
    cvt_kernel<<<(Cc * Cc / 4 + 255) / 256, 256>>>(w2, w2c, Cc * Cc / 4);

    // GEMM1 + bias + GLU
    gemm_mma<true><<<dim3(Cc / 64, Mm / 128), 128>>>(xc, w1c, b1, glup);

    // depthwise LightConv + bias (+ tf32 rounding of z)
    lconv_kernel<<<dim3(Tt / TT, Cc / TC, Bb), 256>>>(glup, lw, lbias, zp);

    // GEMM2 + bias
    gemm_mma<false><<<dim3(Cc / 128, Mm / 128), 128>>>(zp, w2c, b2, out);
}

// round 5
// speedup vs baseline: 2.5989x; 1.1573x over previous
#include <cuda_runtime.h>
#include <cstdint>
#include <math.h>

// Problem constants
#define Bb 16
#define Tt 2048
#define Cc 512
#define Hh 4
#define Kk 31
#define Mm (Bb * Tt)        // 32768 rows

// ---------------- scratch (device globals: allocation-free) ----------------
__device__ float g_xc[(size_t)Mm * Cc];       // tf32-rounded x, 64 MB
__device__ float g_w1c[(size_t)2 * Cc * Cc];  // tf32-rounded w1, 2 MB
__device__ float g_w2c[(size_t)Cc * Cc];      // tf32-rounded w2, 1 MB
__device__ float g_glu[(size_t)Mm * Cc];      // GLU output (fp32), 64 MB
__device__ float g_z[(size_t)Mm * Cc];        // post-conv (tf32-rounded), 64 MB

static __device__ __forceinline__ float f2tf32(float f) {
    uint32_t u;
    asm("cvt.rna.tf32.f32 %0, %1;" : "=r"(u) : "f"(f));
    return __uint_as_float(u);
}

static __device__ __forceinline__ uint32_t smem_u32(const void* p) {
    uint32_t a;
    asm("{ .reg .u64 t; cvta.to.shared.u64 t, %1; cvt.u32.u64 %0, t; }"
        : "=r"(a) : "l"(p));
    return a;
}

#define CP16(d, s) \
    asm volatile("cp.async.cg.shared.global [%0], [%1], 16;" \
                 :: "r"(d), "l"(s) : "memory")

// ---------------- prepass: rna-round to tf32 bit pattern ----------------
__global__ void __launch_bounds__(256) cvt_kernel(
    const float* __restrict__ in, float* __restrict__ out, int n4)
{
    int i = blockIdx.x * blockDim.x + threadIdx.x;
    if (i < n4) {
        float4 v = ((const float4*)in)[i];
        v.x = f2tf32(v.x); v.y = f2tf32(v.y);
        v.z = f2tf32(v.z); v.w = f2tf32(v.w);
        ((float4*)out)[i] = v;
    }
}

// ---------------- tf32 mma.sync GEMM, 64x64 warp tiles, cp.async ----------------
// C[M,N] = A[M,K] @ B[N,K]^T + bias (+GLU).  A,B row-major K-contiguous,
// pre-rounded to tf32.  CTA: 128x128 tile, 128 threads = 4 warps (2x2 of
// 64x64).  BK=16, 4-stage cp.async ring (16KB/stage, 64KB dynamic smem),
// one __syncthreads per chunk.
//
// Smem stage layout (4096 floats): A rows 0..127 x 16 floats, then B.
// float_idx(row,k) = row*16 + ((k>>2) ^ (row&3))*4 + (k&3)   (XOR swizzle)
// mma k-relabel: slot bc <-> storage 2bc, slot bc+4 <-> storage 2bc+1
// (same bijection for A and B => dot product unchanged).
//
// GLU mode: smem B rows [0,32)=a cols cb+[0,32), [32,64)=g for same cols,
// [64,96)=a cols cb+32+[0,32), [96,128)=g for those; epilogue a*sigmoid(g).
#define GEMM_SMEM 65536

template<bool GLU>
__global__ void __launch_bounds__(128, 3) gemm_mma(
    const float* __restrict__ A, const float* __restrict__ Bw,
    const float* __restrict__ bias, float* __restrict__ C)
{
    extern __shared__ __align__(16) float smf[];   // 16384 floats
    const int tid  = threadIdx.x;
    const int lane = tid & 31;
    const int wid  = tid >> 5;
    const int wm   = wid & 1;        // warp m: 0..1 (64 rows)
    const int wn   = wid >> 1;       // warp n: 0..1 (64 cols)
    const int bc   = lane & 3;
    const int lq   = lane >> 2;
    const int m0   = blockIdx.y * 128;
    const int colbase = blockIdx.x * (GLU ? 64 : 128);
    const int NK = Cc / 16;          // 32 chunks

    // ---- producer: thread t -> smem row prow(+32j), 16B unit punit ----
    const int prow  = tid >> 2;
    const int punit = tid & 3;
    const int swu   = (punit ^ (prow & 3)) << 2;
    const uint32_t smu = smem_u32(smf);
    const uint32_t saA = smu + (uint32_t)prow * 64u + (uint32_t)swu * 4u;
    const uint32_t saB = saA + 8192u;
    const char* gA = (const char*)(A + (size_t)(m0 + prow) * Cc + punit * 4);
    const char* gB = (const char*)(Bw + (size_t)(colbase + prow) * Cc + punit * 4);
    // byte offsets of smem-row groups j=0..3 in the B source
    const int BO1 = GLU ? 1048576 : 65536;    // 512*2048  : 32*2048
    const int BO2 = GLU ? 65536   : 131072;   // 32*2048   : 64*2048
    const int BO3 = GLU ? 1114112 : 196608;   // 544*2048  : 96*2048

    float acc[4][8][4];
#pragma unroll
    for (int mt = 0; mt < 4; mt++)
#pragma unroll
        for (int nt = 0; nt < 8; nt++)
#pragma unroll
            for (int i = 0; i < 4; i++) acc[mt][nt][i] = 0.f;

    // consumer loop-invariant offsets (floats)
    const int lq3 = lq & 3;
    const int uo0 = ((((bc >> 1)    ) ^ lq3) << 2) + (bc & 1) * 2;
    const int uo1 = ((((bc >> 1) + 2) ^ lq3) << 2) + (bc & 1) * 2;
    const int aoff = wm * 1024 + lq * 16;
    const int boff = 2048 + wn * 1024 + lq * 16;

    auto issue = [&](int kt) {
        const uint32_t so = (uint32_t)(kt & 3) * 16384u;
        const char* ga = gA + kt * 64;
        const char* gb = gB + kt * 64;
        CP16(saA + so,         ga);
        CP16(saA + so + 2048u, ga + 65536);
        CP16(saA + so + 4096u, ga + 131072);
        CP16(saA + so + 6144u, ga + 196608);
        CP16(saB + so,         gb);
        CP16(saB + so + 2048u, gb + BO1);
        CP16(saB + so + 4096u, gb + BO2);
        CP16(saB + so + 6144u, gb + BO3);
        asm volatile("cp.async.commit_group;" ::: "memory");
    };

    issue(0); issue(1); issue(2);

#pragma unroll 1
    for (int kt = 0; kt < NK; kt++) {
        asm volatile("cp.async.wait_group 2;" ::: "memory");
        __syncthreads();
        if (kt + 3 < NK) issue(kt + 3);
        else asm volatile("cp.async.commit_group;" ::: "memory");

        const float* sA = smf + (kt & 3) * 4096 + aoff;
        const float* sB = smf + (kt & 3) * 4096 + boff;
#pragma unroll
        for (int s = 0; s < 2; s++) {
            const int uo = s ? uo1 : uo0;
            float af[4][4];
#pragma unroll
            for (int mt = 0; mt < 4; mt++) {
                const float2 v0 = *(const float2*)(sA + uo + mt * 256);
                const float2 v1 = *(const float2*)(sA + uo + mt * 256 + 128);
                af[mt][0] = v0.x; af[mt][1] = v1.x;
                af[mt][2] = v0.y; af[mt][3] = v1.y;
            }
#pragma unroll
            for (int nt = 0; nt < 8; nt++) {
                const float2 bv = *(const float2*)(sB + uo + nt * 128);
#pragma unroll
                for (int mt = 0; mt < 4; mt++) {
                    asm volatile(
                        "mma.sync.aligned.m16n8k8.row.col.f32.tf32.tf32.f32 "
                        "{%0,%1,%2,%3}, {%4,%5,%6,%7}, {%8,%9}, {%0,%1,%2,%3};"
                        : "+f"(acc[mt][nt][0]), "+f"(acc[mt][nt][1]),
                          "+f"(acc[mt][nt][2]), "+f"(acc[mt][nt][3])
                        : "r"(__float_as_uint(af[mt][0])), "r"(__float_as_uint(af[mt][1])),
                          "r"(__float_as_uint(af[mt][2])), "r"(__float_as_uint(af[mt][3])),
                          "r"(__float_as_uint(bv.x)), "r"(__float_as_uint(bv.y)));
                }
            }
        }
    }

    // ---- epilogue (identical mapping to R4-verified kernel) ----
    if (GLU) {
#pragma unroll
        for (int mt = 0; mt < 4; mt++) {
            const int r = m0 + wm * 64 + mt * 16 + lq;
#pragma unroll
            for (int nt = 0; nt < 4; nt++) {
                const int col = colbase + wn * 32 + nt * 8 + bc * 2;
                const float2 ba = *(const float2*)&bias[col];
                const float2 bg = *(const float2*)&bias[512 + col];
                float2 o;
                {
                    const float a0 = acc[mt][nt][0] + ba.x, a1 = acc[mt][nt][1] + ba.y;
                    const float g0 = acc[mt][nt + 4][0] + bg.x, g1 = acc[mt][nt + 4][1] + bg.y;
                    o.x = a0 / (1.f + __expf(-g0));
                    o.y = a1 / (1.f + __expf(-g1));
                    *(float2*)&C[(size_t)r * Cc + col] = o;
                }
                {
                    const float a0 = acc[mt][nt][2] + ba.x, a1 = acc[mt][nt][3] + ba.y;
                    const float g0 = acc[mt][nt + 4][2] + bg.x, g1 = acc[mt][nt + 4][3] + bg.y;
                    o.x = a0 / (1.f + __expf(-g0));
                    o.y = a1 / (1.f + __expf(-g1));
                    *(float2*)&C[(size_t)(r + 8) * Cc + col] = o;
                }
            }
        }
    } else {
#pragma unroll
        for (int mt = 0; mt < 4; mt++) {
            const int r = m0 + wm * 64 + mt * 16 + lq;
#pragma unroll
            for (int nt = 0; nt < 8; nt++) {
                const int col = colbase + wn * 64 + nt * 8 + bc * 2;
                const float2 bb = *(const float2*)&bias[col];
                float2 o;
                o.x = acc[mt][nt][0] + bb.x;
                o.y = acc[mt][nt][1] + bb.y;
                *(float2*)&C[(size_t)r * Cc + col] = o;
                o.x = acc[mt][nt][2] + bb.x;
                o.y = acc[mt][nt][3] + bb.y;
                *(float2*)&C[(size_t)(r + 8) * Cc + col] = o;
            }
        }
    }
}

// ---------------- depthwise LightConv (register sliding window) ----------------
#define TT 64
#define TC 64
#define PAD 15
#define SROWS (TT + 2 * PAD)   // 94

__global__ __launch_bounds__(256, 4) void lconv_kernel(
    const float* __restrict__ glu, const float* __restrict__ lw,
    const float* __restrict__ lbias, float* __restrict__ z)
{
    __shared__ float s[SROWS][TC];
    __shared__ float wk[Hh][Kk];

    const int tid = threadIdx.x;
    const int t0 = blockIdx.x * TT;
    const int c0 = blockIdx.y * TC;
    const int b  = blockIdx.z;

    if (tid < Hh) {
        float mx = -1e30f;
#pragma unroll
        for (int k = 0; k < Kk; k++) mx = fmaxf(mx, lw[tid * Kk + k]);
        float sum = 0.f;
        float e[Kk];
#pragma unroll
        for (int k = 0; k < Kk; k++) { e[k] = __expf(lw[tid * Kk + k] - mx); sum += e[k]; }
        const float inv = 1.f / sum;
#pragma unroll
        for (int k = 0; k < Kk; k++) wk[tid][k] = e[k] * inv;
    }

    const float* yb = glu + (size_t)b * Tt * Cc;
    for (int idx = tid; idx < SROWS * (TC / 4); idx += 256) {
        const int r = idx / (TC / 4);
        const int v = idx % (TC / 4);
        const int t = t0 - PAD + r;
        float4 o;
        if (t >= 0 && t < Tt) {
            o = *(const float4*)&yb[(size_t)t * Cc + c0 + v * 4];
        } else {
            o.x = o.y = o.z = o.w = 0.f;
        }
        *(float4*)&s[r][v * 4] = o;
    }
    __syncthreads();

    const int cl = tid & (TC - 1);
    const int tg = tid >> 6;
    const int h  = cl & (Hh - 1);

    float wr[Kk];
#pragma unroll
    for (int k = 0; k < Kk; k++) wr[k] = wk[h][k];
    const float bv = lbias[c0 + cl];

    float acc[16];
#pragma unroll
    for (int i = 0; i < 16; i++) acc[i] = bv;
#pragma unroll
    for (int jj = 0; jj < TT / 4 + Kk - 1; jj++) {
        const float v = s[tg * 16 + jj][cl];
        const int ilo = (jj - (Kk - 1)) > 0 ? (jj - (Kk - 1)) : 0;
        const int ihi = jj < 15 ? jj : 15;
#pragma unroll
        for (int i = ilo; i <= ihi; i++)
            acc[i] += wr[jj - i] * v;
    }

    float* zb = z + ((size_t)b * Tt + t0 + tg * 16) * Cc + c0 + cl;
#pragma unroll
    for (int i = 0; i < 16; i++)
        zb[(size_t)i * Cc] = f2tf32(acc[i]);
}

// ---------------- launch ----------------
extern "C" void kernel_launch(void* const* d_in, const int* in_sizes, int n_in,
                              void* d_out, int out_size)
{
    const float* x     = (const float*)d_in[0];
    const float* lw    = (const float*)d_in[1];
    const float* lbias = (const float*)d_in[2];
    const float* w1    = (const float*)d_in[3];
    const float* b1    = (const float*)d_in[4];
    const float* w2    = (const float*)d_in[5];
    const float* b2    = (const float*)d_in[6];
    float* out = (float*)d_out;

    float *xc, *w1c, *w2c, *glup, *zp;
    cudaGetSymbolAddress((void**)&xc,   g_xc);
    cudaGetSymbolAddress((void**)&w1c,  g_w1c);
    cudaGetSymbolAddress((void**)&w2c,  g_w2c);
    cudaGetSymbolAddress((void**)&glup, g_glu);
    cudaGetSymbolAddress((void**)&zp,   g_z);

    cudaFuncSetAttribute(gemm_mma<true>,
                         cudaFuncAttributeMaxDynamicSharedMemorySize, GEMM_SMEM);
    cudaFuncSetAttribute(gemm_mma<false>,
                         cudaFuncAttributeMaxDynamicSharedMemorySize, GEMM_SMEM);

    // prepass: rna-round inputs once
    cvt_kernel<<<(Mm * Cc / 4 + 255) / 256, 256>>>(x, xc, Mm * Cc / 4);
    cvt_kernel<<<(2 * Cc * Cc / 4 + 255) / 256, 256>>>(w1, w1c, 2 * Cc * Cc / 4);
    cvt_kernel<<<(Cc * Cc / 4 + 255) / 256, 256>>>(w2, w2c, Cc * Cc / 4);

    // GEMM1 + bias + GLU
    gemm_mma<true><<<dim3(Cc / 64, Mm / 128), 128, GEMM_SMEM>>>(xc, w1c, b1, glup);

    // depthwise LightConv + bias (+ tf32 rounding of z)
    lconv_kernel<<<dim3(Tt / TT, Cc / TC, Bb), 256>>>(glup, lw, lbias, zp);

    // GEMM2 + bias
    gemm_mma<false><<<dim3(Cc / 128, Mm / 128), 128, GEMM_SMEM>>>(zp, w2c, b2, out);
}